// round 1
// baseline (speedup 1.0000x reference)
#include <cuda_runtime.h>
#include <math.h>

// Problem constants
#define N_ROWS 4096
#define D_GRP  512
#define V_IN   16
#define U_MID  64
#define H_DIM  8192   // D*V

// ---------------- f32x2 packed-FMA helpers (sm_100+) ----------------
__device__ __forceinline__ unsigned long long pack2(float lo, float hi) {
    unsigned long long r;
    asm("mov.b64 %0, {%1, %2};" : "=l"(r) : "f"(lo), "f"(hi));
    return r;
}
__device__ __forceinline__ unsigned long long ffma2(unsigned long long a,
                                                    unsigned long long b,
                                                    unsigned long long c) {
    unsigned long long d;
    asm("fma.rn.f32x2 %0, %1, %2, %3;" : "=l"(d) : "l"(a), "l"(b), "l"(c));
    return d;
}
__device__ __forceinline__ float2 unpack2(unsigned long long v) {
    float2 f;
    asm("mov.b64 {%0, %1}, %2;" : "=f"(f.x), "=f"(f.y) : "l"(v));
    return f;
}

__device__ __forceinline__ float elu1(float v) {
    return v > 0.0f ? v : (__expf(v) - 1.0f);
}

// ---------------------------------------------------------------------------
// Kernel 1: grouped conv1 + ELU + grouped conv2 + b2  ->  y[N, D] (unnormalized)
//
// Grid:  (N/128, D/4).  Block: 128 threads = 4 warps.
// Warp g handles group d = blockIdx.y*4 + g for 128 rows (lane + 32*j).
// W1 for the 4 groups lives in shared, duplicated as (w,w) u64 pairs so
// LDS.128 feeds fma.rn.f32x2 directly (warp-uniform address -> broadcast).
// ---------------------------------------------------------------------------
__global__ void __launch_bounds__(128)
div_encoder_main(const float* __restrict__ x,
                 const float* __restrict__ W1,
                 const float* __restrict__ b1,
                 const float* __restrict__ W2,
                 const float* __restrict__ b2,
                 float* __restrict__ out)
{
    // shared: duplicated W1 (4 groups * 64u * 16v pairs = 32 KB), b1 pairs, W2 scalars
    __shared__ ulonglong2         w1s[4 * U_MID * 8];   // [g][u][v2] : 2 dup-pairs each
    __shared__ unsigned long long b1s[4 * U_MID];
    __shared__ float              w2s[4 * U_MID];

    const int tid   = threadIdx.x;
    const int gbase = blockIdx.y * 4;

    // cooperative load of weights for the 4 groups of this block
    {
        unsigned long long* w1flat = reinterpret_cast<unsigned long long*>(w1s);
        const float* w1g = W1 + (size_t)gbase * (U_MID * V_IN);
        #pragma unroll
        for (int i = tid; i < 4 * U_MID * V_IN; i += 128) {
            float w = w1g[i];
            w1flat[i] = pack2(w, w);
        }
        const float* b1g = b1 + gbase * U_MID;
        const float* w2g = W2 + gbase * U_MID;
        for (int i = tid; i < 4 * U_MID; i += 128) {
            float b = b1g[i];
            b1s[i] = pack2(b, b);
            w2s[i] = w2g[i];
        }
    }
    __syncthreads();

    const int g    = tid >> 5;        // warp id = group within block
    const int lane = tid & 31;
    const int d    = gbase + g;
    const int r0   = blockIdx.x * 128 + lane;   // rows r0, r0+32, r0+64, r0+96

    // load x slices for the 4 rows (16 floats each) and pack row-pairs
    unsigned long long x2a[16], x2b[16];
    {
        const float* xb = x + (size_t)r0 * H_DIM + d * V_IN;
        float4 ra[4], rb[4], rc[4], rd[4];
        const float4* p0 = reinterpret_cast<const float4*>(xb);
        const float4* p1 = reinterpret_cast<const float4*>(xb + (size_t)32 * H_DIM);
        const float4* p2 = reinterpret_cast<const float4*>(xb + (size_t)64 * H_DIM);
        const float4* p3 = reinterpret_cast<const float4*>(xb + (size_t)96 * H_DIM);
        #pragma unroll
        for (int k = 0; k < 4; ++k) { ra[k] = p0[k]; rb[k] = p1[k]; rc[k] = p2[k]; rd[k] = p3[k]; }
        #pragma unroll
        for (int k = 0; k < 4; ++k) {
            const float* fa = reinterpret_cast<const float*>(&ra[k]);
            const float* fb = reinterpret_cast<const float*>(&rb[k]);
            const float* fc = reinterpret_cast<const float*>(&rc[k]);
            const float* fd = reinterpret_cast<const float*>(&rd[k]);
            #pragma unroll
            for (int e = 0; e < 4; ++e) {
                x2a[k * 4 + e] = pack2(fa[e], fb[e]);
                x2b[k * 4 + e] = pack2(fc[e], fd[e]);
            }
        }
    }

    float y0 = 0.f, y1 = 0.f, y2 = 0.f, y3 = 0.f;
    const ulonglong2*         wbase = w1s + g * (U_MID * 8);
    const unsigned long long* bbase = b1s + g * U_MID;
    const float*              sbase = w2s + g * U_MID;

    #pragma unroll 4
    for (int u = 0; u < U_MID; ++u) {
        unsigned long long acc_a = bbase[u];
        unsigned long long acc_b = acc_a;
        const ulonglong2* wr = wbase + u * 8;
        #pragma unroll
        for (int v2 = 0; v2 < 8; ++v2) {
            ulonglong2 w = wr[v2];
            acc_a = ffma2(x2a[2 * v2],     w.x, acc_a);
            acc_b = ffma2(x2b[2 * v2],     w.x, acc_b);
            acc_a = ffma2(x2a[2 * v2 + 1], w.y, acc_a);
            acc_b = ffma2(x2b[2 * v2 + 1], w.y, acc_b);
        }
        float2 ha = unpack2(acc_a);
        float2 hb = unpack2(acc_b);
        float w2u = sbase[u];
        y0 = fmaf(elu1(ha.x), w2u, y0);
        y1 = fmaf(elu1(ha.y), w2u, y1);
        y2 = fmaf(elu1(hb.x), w2u, y2);
        y3 = fmaf(elu1(hb.y), w2u, y3);
    }

    const float bb = b2[d];
    out[(size_t)(r0      ) * D_GRP + d] = y0 + bb;
    out[(size_t)(r0 + 32 ) * D_GRP + d] = y1 + bb;
    out[(size_t)(r0 + 64 ) * D_GRP + d] = y2 + bb;
    out[(size_t)(r0 + 96 ) * D_GRP + d] = y3 + bb;
}

// ---------------------------------------------------------------------------
// Kernel 2: in-place row L2 normalize  y[n,:] /= max(||y[n,:]||, 1e-12)
// One block (128 threads) per row; each thread owns one float4 (512 floats).
// ---------------------------------------------------------------------------
__global__ void __launch_bounds__(128)
div_encoder_norm(float* __restrict__ y)
{
    const int row = blockIdx.x;
    const int tid = threadIdx.x;
    float4* rp = reinterpret_cast<float4*>(y + (size_t)row * D_GRP);
    float4 v = rp[tid];
    float s = v.x * v.x + v.y * v.y + v.z * v.z + v.w * v.w;

    #pragma unroll
    for (int off = 16; off > 0; off >>= 1)
        s += __shfl_xor_sync(0xFFFFFFFFu, s, off);

    __shared__ float ws[4];
    if ((tid & 31) == 0) ws[tid >> 5] = s;
    __syncthreads();
    s = ws[0] + ws[1] + ws[2] + ws[3];

    const float scale = 1.0f / fmaxf(sqrtf(s), 1e-12f);
    v.x *= scale; v.y *= scale; v.z *= scale; v.w *= scale;
    rp[tid] = v;
}

extern "C" void kernel_launch(void* const* d_in, const int* in_sizes, int n_in,
                              void* d_out, int out_size)
{
    const float* x  = (const float*)d_in[0];
    const float* W1 = (const float*)d_in[1];
    const float* b1 = (const float*)d_in[2];
    const float* W2 = (const float*)d_in[3];
    const float* b2 = (const float*)d_in[4];
    float* out = (float*)d_out;

    dim3 grid1(N_ROWS / 128, D_GRP / 4);
    div_encoder_main<<<grid1, 128>>>(x, W1, b1, W2, b2, out);
    div_encoder_norm<<<N_ROWS, 128>>>(out);
}

// round 2
// speedup vs baseline: 1.0935x; 1.0935x over previous
#include <cuda_runtime.h>
#include <math.h>

// Problem constants
#define N_ROWS 4096
#define D_GRP  512
#define V_IN   16
#define U_MID  64
#define H_DIM  8192   // D*V

// ---------------- f32x2 packed helpers (sm_100+) ----------------
__device__ __forceinline__ unsigned long long pack2(float lo, float hi) {
    unsigned long long r;
    asm("mov.b64 %0, {%1, %2};" : "=l"(r) : "f"(lo), "f"(hi));
    return r;
}
__device__ __forceinline__ unsigned long long ffma2(unsigned long long a,
                                                    unsigned long long b,
                                                    unsigned long long c) {
    unsigned long long d;
    asm("fma.rn.f32x2 %0, %1, %2, %3;" : "=l"(d) : "l"(a), "l"(b), "l"(c));
    return d;
}
__device__ __forceinline__ unsigned long long fmul2(unsigned long long a,
                                                    unsigned long long b) {
    unsigned long long d;
    asm("mul.rn.f32x2 %0, %1, %2;" : "=l"(d) : "l"(a), "l"(b));
    return d;
}
__device__ __forceinline__ unsigned long long fadd2(unsigned long long a,
                                                    unsigned long long b) {
    unsigned long long d;
    asm("add.rn.f32x2 %0, %1, %2;" : "=l"(d) : "l"(a), "l"(b));
    return d;
}
__device__ __forceinline__ float2 unpack2(unsigned long long v) {
    float2 f;
    asm("mov.b64 {%0, %1}, %2;" : "=f"(f.x), "=f"(f.y) : "l"(v));
    return f;
}
__device__ __forceinline__ float ex2(float v) {
    float r;
    asm("ex2.approx.f32 %0, %1;" : "=f"(r) : "f"(v));
    return r;
}

// Branchless packed ELU:  elu(v) = max(v, exp(min(v,0)) - 1)
// (exact: for v<=0, e^v-1 >= v so max picks e^v-1; for v>0, exp(0)-1=0 < v)
__device__ __forceinline__ unsigned long long elu2(unsigned long long acc) {
    const unsigned long long LOG2E2 = pack2(1.4426950408889634f, 1.4426950408889634f);
    const unsigned long long NEG1_2 = pack2(-1.0f, -1.0f);
    float2 a = unpack2(acc);
    float t0 = fminf(a.x, 0.0f);
    float t1 = fminf(a.y, 0.0f);
    unsigned long long sp = fmul2(pack2(t0, t1), LOG2E2);   // t * log2(e)  (packed, fma pipe)
    float2 s = unpack2(sp);
    float e0 = ex2(s.x);                                    // MUFU pipe
    float e1 = ex2(s.y);
    unsigned long long ep = fadd2(pack2(e0, e1), NEG1_2);   // e - 1 (packed)
    float2 e = unpack2(ep);
    float r0 = fmaxf(a.x, e.x);                             // alu pipe
    float r1 = fmaxf(a.y, e.y);
    return pack2(r0, r1);
}

// ---------------------------------------------------------------------------
// Kernel 1: grouped conv1 + ELU + grouped conv2 + b2  ->  y[N, D] (unnormalized)
// Grid: (N/128, D/4). Block 128 = 4 warps; warp g owns group d = blockIdx.y*4+g
// for 128 rows. W1 duplicated as (w,w) u64 pairs in smem -> LDS.128 broadcast
// feeds fma.rn.f32x2 directly.
// ---------------------------------------------------------------------------
__global__ void __launch_bounds__(128)
div_encoder_main(const float* __restrict__ x,
                 const float* __restrict__ W1,
                 const float* __restrict__ b1,
                 const float* __restrict__ W2,
                 const float* __restrict__ b2,
                 float* __restrict__ out)
{
    __shared__ ulonglong2         w1s[4 * U_MID * 8];   // 32 KB dup pairs
    __shared__ unsigned long long b1s[4 * U_MID];       // dup pairs
    __shared__ unsigned long long w2s[4 * U_MID];       // dup pairs
    __shared__ float              outs[128][5];         // padded transpose buffer

    const int tid   = threadIdx.x;
    const int gbase = blockIdx.y * 4;

    {
        unsigned long long* w1flat = reinterpret_cast<unsigned long long*>(w1s);
        const float* w1g = W1 + (size_t)gbase * (U_MID * V_IN);
        #pragma unroll
        for (int i = tid; i < 4 * U_MID * V_IN; i += 128) {
            float w = w1g[i];
            w1flat[i] = pack2(w, w);
        }
        const float* b1g = b1 + gbase * U_MID;
        const float* w2g = W2 + gbase * U_MID;
        for (int i = tid; i < 4 * U_MID; i += 128) {
            float b = b1g[i];
            b1s[i] = pack2(b, b);
            float w = w2g[i];
            w2s[i] = pack2(w, w);
        }
    }
    __syncthreads();

    const int g    = tid >> 5;
    const int lane = tid & 31;
    const int d    = gbase + g;
    const int r0   = blockIdx.x * 128 + lane;   // rows r0, r0+32, r0+64, r0+96

    // load x slices for the 4 rows (16 floats each) and pack row-pairs
    unsigned long long x2a[16], x2b[16];
    {
        const float* xb = x + (size_t)r0 * H_DIM + d * V_IN;
        float4 ra[4], rb[4], rc[4], rd[4];
        const float4* p0 = reinterpret_cast<const float4*>(xb);
        const float4* p1 = reinterpret_cast<const float4*>(xb + (size_t)32 * H_DIM);
        const float4* p2 = reinterpret_cast<const float4*>(xb + (size_t)64 * H_DIM);
        const float4* p3 = reinterpret_cast<const float4*>(xb + (size_t)96 * H_DIM);
        #pragma unroll
        for (int k = 0; k < 4; ++k) { ra[k] = p0[k]; rb[k] = p1[k]; rc[k] = p2[k]; rd[k] = p3[k]; }
        #pragma unroll
        for (int k = 0; k < 4; ++k) {
            const float* fa = reinterpret_cast<const float*>(&ra[k]);
            const float* fb = reinterpret_cast<const float*>(&rb[k]);
            const float* fc = reinterpret_cast<const float*>(&rc[k]);
            const float* fd = reinterpret_cast<const float*>(&rd[k]);
            #pragma unroll
            for (int e = 0; e < 4; ++e) {
                x2a[k * 4 + e] = pack2(fa[e], fb[e]);
                x2b[k * 4 + e] = pack2(fc[e], fd[e]);
            }
        }
    }

    unsigned long long y_a = 0ull, y_b = 0ull;  // packed row-pair accumulators (0.0f,0.0f)
    const ulonglong2*         wbase = w1s + g * (U_MID * 8);
    const unsigned long long* bbase = b1s + g * U_MID;
    const unsigned long long* sbase = w2s + g * U_MID;

    #pragma unroll 4
    for (int u = 0; u < U_MID; ++u) {
        unsigned long long acc_a = bbase[u];
        unsigned long long acc_b = acc_a;
        const ulonglong2* wr = wbase + u * 8;
        #pragma unroll
        for (int v2 = 0; v2 < 8; ++v2) {
            ulonglong2 w = wr[v2];
            acc_a = ffma2(x2a[2 * v2],     w.x, acc_a);
            acc_b = ffma2(x2b[2 * v2],     w.x, acc_b);
            acc_a = ffma2(x2a[2 * v2 + 1], w.y, acc_a);
            acc_b = ffma2(x2b[2 * v2 + 1], w.y, acc_b);
        }
        unsigned long long w2u = sbase[u];
        y_a = ffma2(elu2(acc_a), w2u, y_a);
        y_b = ffma2(elu2(acc_b), w2u, y_b);
    }

    // stage to smem (padded, conflict-free), then coalesced float4 row writes
    {
        float2 ya = unpack2(y_a);
        float2 yb = unpack2(y_b);
        outs[lane      ][g] = ya.x;
        outs[lane + 32 ][g] = ya.y;
        outs[lane + 64 ][g] = yb.x;
        outs[lane + 96 ][g] = yb.y;
    }
    __syncthreads();

    {
        const float4 bv = *reinterpret_cast<const float4*>(b2 + gbase);
        float4 v;
        v.x = outs[tid][0] + bv.x;
        v.y = outs[tid][1] + bv.y;
        v.z = outs[tid][2] + bv.z;
        v.w = outs[tid][3] + bv.w;
        const int row = blockIdx.x * 128 + tid;
        *reinterpret_cast<float4*>(out + (size_t)row * D_GRP + gbase) = v;
    }
}

// ---------------------------------------------------------------------------
// Kernel 2: in-place row L2 normalize, one warp per row (no barriers/smem).
// Block 256 = 8 warps = 8 rows; grid = N/8 = 512.
// ---------------------------------------------------------------------------
__global__ void __launch_bounds__(256)
div_encoder_norm(float* __restrict__ y)
{
    const int row  = blockIdx.x * 8 + (threadIdx.x >> 5);
    const int lane = threadIdx.x & 31;
    float4* rp = reinterpret_cast<float4*>(y + (size_t)row * D_GRP);

    float4 v0 = rp[lane];
    float4 v1 = rp[lane + 32];
    float4 v2 = rp[lane + 64];
    float4 v3 = rp[lane + 96];

    float s = v0.x*v0.x + v0.y*v0.y + v0.z*v0.z + v0.w*v0.w
            + v1.x*v1.x + v1.y*v1.y + v1.z*v1.z + v1.w*v1.w
            + v2.x*v2.x + v2.y*v2.y + v2.z*v2.z + v2.w*v2.w
            + v3.x*v3.x + v3.y*v3.y + v3.z*v3.z + v3.w*v3.w;

    #pragma unroll
    for (int off = 16; off > 0; off >>= 1)
        s += __shfl_xor_sync(0xFFFFFFFFu, s, off);

    const float scale = 1.0f / fmaxf(sqrtf(s), 1e-12f);
    v0.x *= scale; v0.y *= scale; v0.z *= scale; v0.w *= scale;
    v1.x *= scale; v1.y *= scale; v1.z *= scale; v1.w *= scale;
    v2.x *= scale; v2.y *= scale; v2.z *= scale; v2.w *= scale;
    v3.x *= scale; v3.y *= scale; v3.z *= scale; v3.w *= scale;
    rp[lane]      = v0;
    rp[lane + 32] = v1;
    rp[lane + 64] = v2;
    rp[lane + 96] = v3;
}

// Launch-sequence pad so ncu (-s 5 -c 1) lands on the MAIN kernel:
// pattern per call = (nop, main, norm, nop) -> launch idx 5 = 5 mod 4 = 1 = main.
__global__ void div_encoder_nop() {}

extern "C" void kernel_launch(void* const* d_in, const int* in_sizes, int n_in,
                              void* d_out, int out_size)
{
    const float* x  = (const float*)d_in[0];
    const float* W1 = (const float*)d_in[1];
    const float* b1 = (const float*)d_in[2];
    const float* W2 = (const float*)d_in[3];
    const float* b2 = (const float*)d_in[4];
    float* out = (float*)d_out;

    div_encoder_nop<<<1, 32>>>();
    dim3 grid1(N_ROWS / 128, D_GRP / 4);
    div_encoder_main<<<grid1, 128>>>(x, W1, b1, W2, b2, out);
    div_encoder_norm<<<N_ROWS / 8, 256>>>(out);
    div_encoder_nop<<<1, 32>>>();
}

// round 3
// speedup vs baseline: 1.1068x; 1.0122x over previous
#include <cuda_runtime.h>
#include <math.h>

// Problem constants
#define N_ROWS 4096
#define D_GRP  512
#define V_IN   16
#define U_MID  64
#define H_DIM  8192   // D*V

// ---------------- f32x2 packed helpers (sm_100+) ----------------
__device__ __forceinline__ unsigned long long pack2(float lo, float hi) {
    unsigned long long r;
    asm("mov.b64 %0, {%1, %2};" : "=l"(r) : "f"(lo), "f"(hi));
    return r;
}
__device__ __forceinline__ unsigned long long ffma2(unsigned long long a,
                                                    unsigned long long b,
                                                    unsigned long long c) {
    unsigned long long d;
    asm("fma.rn.f32x2 %0, %1, %2, %3;" : "=l"(d) : "l"(a), "l"(b), "l"(c));
    return d;
}
__device__ __forceinline__ float2 unpack2(unsigned long long v) {
    float2 f;
    asm("mov.b64 {%0, %1}, %2;" : "=f"(f.x), "=f"(f.y) : "l"(v));
    return f;
}
__device__ __forceinline__ float ex2(float v) {
    float r;
    asm("ex2.approx.f32 %0, %1;" : "=f"(r) : "f"(v));
    return r;
}

// Minimal-op branchless ELU: 1 FMNMX + 1 FMUL + 1 MUFU + 1 FADD + 1 FMNMX.
// elu(v) = max(v, exp(min(v,0)) - 1)  (exact identity; min-clamp avoids inf)
__device__ __forceinline__ float eluf(float v) {
    float t = fminf(v, 0.0f);
    float e = ex2(t * 1.4426950408889634f);
    return fmaxf(v, e - 1.0f);
}

// ---------------------------------------------------------------------------
// Kernel 1: grouped conv1 + ELU + grouped conv2 + b2  ->  y[N, D] (unnormalized)
// Grid: (N/128, D/4). Block 128 = 4 warps; warp g owns group d = blockIdx.y*4+g
// for 128 rows (4 per thread, packed as 2 row-pair f32x2 accumulators).
// W1 duplicated as (w,w) u64 pairs in smem -> LDS.128 broadcast feeds
// fma.rn.f32x2 directly. Epilogue is fully scalar (no pack/unpack traffic).
// ---------------------------------------------------------------------------
__global__ void __launch_bounds__(128)
div_encoder_main(const float* __restrict__ x,
                 const float* __restrict__ W1,
                 const float* __restrict__ b1,
                 const float* __restrict__ W2,
                 const float* __restrict__ b2,
                 float* __restrict__ out)
{
    __shared__ ulonglong2         w1s[4 * U_MID * 8];   // 32 KB dup pairs
    __shared__ unsigned long long b1s[4 * U_MID];       // dup pairs
    __shared__ float              w2s[4 * U_MID];       // scalars
    __shared__ float              outs[128][5];         // padded transpose buffer

    const int tid   = threadIdx.x;
    const int gbase = blockIdx.y * 4;

    {
        unsigned long long* w1flat = reinterpret_cast<unsigned long long*>(w1s);
        const float* w1g = W1 + (size_t)gbase * (U_MID * V_IN);
        #pragma unroll
        for (int i = tid; i < 4 * U_MID * V_IN; i += 128) {
            float w = w1g[i];
            w1flat[i] = pack2(w, w);
        }
        const float* b1g = b1 + gbase * U_MID;
        const float* w2g = W2 + gbase * U_MID;
        for (int i = tid; i < 4 * U_MID; i += 128) {
            float b = b1g[i];
            b1s[i] = pack2(b, b);
            w2s[i] = w2g[i];
        }
    }
    __syncthreads();

    const int g    = tid >> 5;
    const int lane = tid & 31;
    const int d    = gbase + g;
    const int r0   = blockIdx.x * 128 + lane;   // rows r0, r0+32, r0+64, r0+96

    // load x slices for the 4 rows (16 floats each) and pack row-pairs
    unsigned long long x2a[16], x2b[16];
    {
        const float* xb = x + (size_t)r0 * H_DIM + d * V_IN;
        float4 ra[4], rb[4], rc[4], rd[4];
        const float4* p0 = reinterpret_cast<const float4*>(xb);
        const float4* p1 = reinterpret_cast<const float4*>(xb + (size_t)32 * H_DIM);
        const float4* p2 = reinterpret_cast<const float4*>(xb + (size_t)64 * H_DIM);
        const float4* p3 = reinterpret_cast<const float4*>(xb + (size_t)96 * H_DIM);
        #pragma unroll
        for (int k = 0; k < 4; ++k) { ra[k] = p0[k]; rb[k] = p1[k]; rc[k] = p2[k]; rd[k] = p3[k]; }
        #pragma unroll
        for (int k = 0; k < 4; ++k) {
            const float* fa = reinterpret_cast<const float*>(&ra[k]);
            const float* fb = reinterpret_cast<const float*>(&rb[k]);
            const float* fc = reinterpret_cast<const float*>(&rc[k]);
            const float* fd = reinterpret_cast<const float*>(&rd[k]);
            #pragma unroll
            for (int e = 0; e < 4; ++e) {
                x2a[k * 4 + e] = pack2(fa[e], fb[e]);
                x2b[k * 4 + e] = pack2(fc[e], fd[e]);
            }
        }
    }

    float y0 = 0.f, y1 = 0.f, y2 = 0.f, y3 = 0.f;   // scalar row accumulators
    const ulonglong2*         wbase = w1s + g * (U_MID * 8);
    const unsigned long long* bbase = b1s + g * U_MID;
    const float*              sbase = w2s + g * U_MID;

    #pragma unroll 4
    for (int u = 0; u < U_MID; ++u) {
        unsigned long long acc_a = bbase[u];
        unsigned long long acc_b = acc_a;
        const ulonglong2* wr = wbase + u * 8;
        #pragma unroll
        for (int v2 = 0; v2 < 8; ++v2) {
            ulonglong2 w = wr[v2];
            acc_a = ffma2(x2a[2 * v2],     w.x, acc_a);
            acc_b = ffma2(x2b[2 * v2],     w.x, acc_b);
            acc_a = ffma2(x2a[2 * v2 + 1], w.y, acc_a);
            acc_b = ffma2(x2b[2 * v2 + 1], w.y, acc_b);
        }
        // fully scalar epilogue: 3 fma-pipe + 2 alu + 1 mufu per element
        const float w2u = sbase[u];
        float2 ha = unpack2(acc_a);
        float2 hb = unpack2(acc_b);
        y0 = fmaf(eluf(ha.x), w2u, y0);
        y1 = fmaf(eluf(ha.y), w2u, y1);
        y2 = fmaf(eluf(hb.x), w2u, y2);
        y3 = fmaf(eluf(hb.y), w2u, y3);
    }

    // stage to smem (padded, conflict-free), then coalesced float4 row writes
    outs[lane      ][g] = y0;
    outs[lane + 32 ][g] = y1;
    outs[lane + 64 ][g] = y2;
    outs[lane + 96 ][g] = y3;
    __syncthreads();

    {
        const float4 bv = *reinterpret_cast<const float4*>(b2 + gbase);
        float4 v;
        v.x = outs[tid][0] + bv.x;
        v.y = outs[tid][1] + bv.y;
        v.z = outs[tid][2] + bv.z;
        v.w = outs[tid][3] + bv.w;
        const int row = blockIdx.x * 128 + tid;
        *reinterpret_cast<float4*>(out + (size_t)row * D_GRP + gbase) = v;
    }
}

// ---------------------------------------------------------------------------
// Kernel 2: in-place row L2 normalize, one warp per row (no barriers/smem).
// Block 256 = 8 warps = 8 rows; grid = N/8 = 512.
// ---------------------------------------------------------------------------
__global__ void __launch_bounds__(256)
div_encoder_norm(float* __restrict__ y)
{
    const int row  = blockIdx.x * 8 + (threadIdx.x >> 5);
    const int lane = threadIdx.x & 31;
    float4* rp = reinterpret_cast<float4*>(y + (size_t)row * D_GRP);

    float4 v0 = rp[lane];
    float4 v1 = rp[lane + 32];
    float4 v2 = rp[lane + 64];
    float4 v3 = rp[lane + 96];

    float s = v0.x*v0.x + v0.y*v0.y + v0.z*v0.z + v0.w*v0.w
            + v1.x*v1.x + v1.y*v1.y + v1.z*v1.z + v1.w*v1.w
            + v2.x*v2.x + v2.y*v2.y + v2.z*v2.z + v2.w*v2.w
            + v3.x*v3.x + v3.y*v3.y + v3.z*v3.z + v3.w*v3.w;

    #pragma unroll
    for (int off = 16; off > 0; off >>= 1)
        s += __shfl_xor_sync(0xFFFFFFFFu, s, off);

    const float scale = 1.0f / fmaxf(sqrtf(s), 1e-12f);
    v0.x *= scale; v0.y *= scale; v0.z *= scale; v0.w *= scale;
    v1.x *= scale; v1.y *= scale; v1.z *= scale; v1.w *= scale;
    v2.x *= scale; v2.y *= scale; v2.z *= scale; v2.w *= scale;
    v3.x *= scale; v3.y *= scale; v3.z *= scale; v3.w *= scale;
    rp[lane]      = v0;
    rp[lane + 32] = v1;
    rp[lane + 64] = v2;
    rp[lane + 96] = v3;
}

extern "C" void kernel_launch(void* const* d_in, const int* in_sizes, int n_in,
                              void* d_out, int out_size)
{
    const float* x  = (const float*)d_in[0];
    const float* W1 = (const float*)d_in[1];
    const float* b1 = (const float*)d_in[2];
    const float* W2 = (const float*)d_in[3];
    const float* b2 = (const float*)d_in[4];
    float* out = (float*)d_out;

    dim3 grid1(N_ROWS / 128, D_GRP / 4);
    div_encoder_main<<<grid1, 128>>>(x, W1, b1, W2, b2, out);
    div_encoder_norm<<<N_ROWS / 8, 256>>>(out);
}